// round 2
// baseline (speedup 1.0000x reference)
#include <cuda_runtime.h>
#include <cuda_bf16.h>
#include <cstdint>

#define BDIM 16384
#define CDIM 1000
#define CP   1024
#define SPLITK 8
#define KCHUNK (BDIM / SPLITK)     // 2048
#define MAIN_BLOCKS (BDIM / 8)     // 2048 blocks, warp-per-row
#define CORR_BLOCKS 512

// ---------------- static scratch (no dynamic allocation allowed) ----------------
__device__ float          g_colsumPart[8 * CP];
__device__ float          g_rcp[CP];                       // 1/colsum[d]
__device__ float          g_rowsumM[CP];                   // sum_d M[c,d]
__device__ __nv_bfloat16  g_Y[(size_t)BDIM * CP];          // y (bf16), zero-padded to 1024 cols
__device__ __nv_bfloat16  g_V[(size_t)BDIM * CP];          // V = y*w*h(sigma)/rs  (bf16)
__device__ float          g_Gpart[SPLITK][(size_t)CP * CP];
__device__ float          g_basePart[MAIN_BLOCKS];
__device__ float          g_corrPart[CORR_BLOCKS];

__device__ __forceinline__ float warpRed(float v) {
    #pragma unroll
    for (int o = 16; o; o >>= 1) v += __shfl_xor_sync(0xffffffffu, v, o);
    return v;
}

// ---------------- K1a: partial column sums of co ----------------
__global__ void k_colsum_part(const float* __restrict__ co) {
    int d  = blockIdx.x * 256 + threadIdx.x;   // 0..1023
    int c0 = blockIdx.y * 125;
    float s = 0.f;
    if (d < CDIM) {
        #pragma unroll 5
        for (int c = c0; c < c0 + 125; c++) s += co[(size_t)c * CDIM + d];
    }
    g_colsumPart[blockIdx.y * CP + d] = s;
}

// ---------------- K1b: finalize colsum -> reciprocal ----------------
__global__ void k_finalize_colsum() {
    int d = threadIdx.x;
    float s = 0.f;
    #pragma unroll
    for (int j = 0; j < 8; j++) s += g_colsumPart[j * CP + d];
    g_rcp[d] = (d < CDIM) ? (1.0f / s) : 0.f;
}

// ---------------- K1c: rowsumM[c] = sum_d co[c,d] * rcp[d] ----------------
__global__ void k_rowsumM(const float* __restrict__ co) {
    __shared__ float red[4];
    int c = blockIdx.x;
    float s = 0.f;
    for (int d = threadIdx.x; d < CDIM; d += 128)
        s += co[(size_t)c * CDIM + d] * g_rcp[d];
    s = warpRed(s);
    int warp = threadIdx.x >> 5, lane = threadIdx.x & 31;
    if (lane == 0) red[warp] = s;
    __syncthreads();
    if (threadIdx.x == 0) g_rowsumM[c] = red[0] + red[1] + red[2] + red[3];
}

// ---------------- K2: fused main pass (warp per row) ----------------
// rs_b = y . rowsumM ; base-loss terms ; V = y*w*h(sigma)/rs (bf16) ; Y bf16
__global__ __launch_bounds__(256) void k_main(const float* __restrict__ x,
                                              const float* __restrict__ y,
                                              const float* __restrict__ w) {
    __shared__ float s_rsm[CP];
    __shared__ float s_w[CP];
    __shared__ float s_red[8];
    for (int i = threadIdx.x; i < CP; i += 256) {
        s_rsm[i] = (i < CDIM) ? g_rowsumM[i] : 0.f;
        s_w[i]   = (i < CDIM) ? w[i] : 0.f;
    }
    __syncthreads();

    int warp = threadIdx.x >> 5, lane = threadIdx.x & 31;
    size_t b = (size_t)blockIdx.x * 8 + warp;
    const float* xrow = x + b * CDIM;
    const float* yrow = y + b * CDIM;

    // pass 1: rs = y . rowsumM
    float rs = 0.f;
    #pragma unroll 8
    for (int k = 0; k < 32; k++) {
        int c = k * 32 + lane;
        if (c < CDIM) rs += yrow[c] * s_rsm[c];
    }
    rs = warpRed(rs);
    float rinv = __fdividef(1.0f, rs);

    __nv_bfloat16* Yo = g_Y + b * CP;
    __nv_bfloat16* Vo = g_V + b * CP;

    float base = 0.f;
    #pragma unroll 4
    for (int k = 0; k < 32; k++) {
        int c = k * 32 + lane;                 // c in [0,1024)
        float Vv = 0.f;
        float Yv = 0.f;
        if (c < CDIM) {
            float wv = s_w[c];
            float xv = xrow[c];
            float yc = yrow[c];
            Yv = yc;
            float t   = __expf(-xv);
            float inv = __fdividef(1.f, 1.f + t);   // sigma
            float sig = inv;
            float onems = t * inv;                  // 1 - sigma
            if (yc > 0.5f) {
                float logsig = -__logf(1.f + t);
                base += wv * logsig * onems;
                float h = sig * logsig - onems;     // d(loss)/d(att) factor
                Vv = wv * h * rinv;
            } else {
                float xn  = fminf(onems + 0.05f, 1.f);
                float xn2 = fminf(xn * 1.2f, 1.f);
                float tn  = 1.f - xn2;
                if (tn > 0.f)
                    base += wv * __logf(xn2) * __powf(tn, 3.f + wv);
            }
        }
        Yo[c] = __float2bfloat16(Yv);
        Vo[c] = __float2bfloat16(Vv);
    }
    base = warpRed(base);
    if (lane == 0) s_red[warp] = base;
    __syncthreads();
    if (threadIdx.x == 0) {
        float s = 0.f;
        #pragma unroll
        for (int i = 0; i < 8; i++) s += s_red[i];
        g_basePart[blockIdx.x] = s;
    }
}

// ---------------- K3: G = Y^T V  (bf16 mma.sync, split-K) ----------------
#define BK 32
#define SROW (128 + 8)

__device__ __forceinline__ void ldm4t(uint32_t* r, uint32_t addr) {
    asm volatile("ldmatrix.sync.aligned.m8n8.x4.trans.shared.b16 {%0,%1,%2,%3}, [%4];"
                 : "=r"(r[0]), "=r"(r[1]), "=r"(r[2]), "=r"(r[3]) : "r"(addr));
}
__device__ __forceinline__ void mma16816(float* d, const uint32_t* a, const uint32_t* b) {
    asm volatile("mma.sync.aligned.m16n8k16.row.col.f32.bf16.bf16.f32 "
                 "{%0,%1,%2,%3}, {%4,%5,%6,%7}, {%8,%9}, {%0,%1,%2,%3};"
                 : "+f"(d[0]), "+f"(d[1]), "+f"(d[2]), "+f"(d[3])
                 : "r"(a[0]), "r"(a[1]), "r"(a[2]), "r"(a[3]), "r"(b[0]), "r"(b[1]));
}

__global__ __launch_bounds__(256, 2) void k_gemm() {
    __shared__ __align__(16) __nv_bfloat16 sY[BK][SROW];
    __shared__ __align__(16) __nv_bfloat16 sV[BK][SROW];

    int tid  = threadIdx.x;
    int lane = tid & 31, warp = tid >> 5;
    int wm = warp & 3;            // 4 warps along M (32 rows each)
    int wn = warp >> 2;           // 2 warps along N (64 cols each)
    int cm = blockIdx.y * 128;    // M tile (c)
    int n0 = blockIdx.x * 128;    // N tile (d)
    size_t k0 = (size_t)blockIdx.z * KCHUNK;

    int lr = tid >> 3;            // smem row 0..31
    int lc = (tid & 7) * 16;      // smem col (bf16 units): 16 per thread

    const __nv_bfloat16* pY = g_Y + (k0 + lr) * CP + cm + lc;
    const __nv_bfloat16* pV = g_V + (k0 + lr) * CP + n0 + lc;

    uint4 rY0 = *(const uint4*)pY, rY1 = *(const uint4*)(pY + 8);
    uint4 rV0 = *(const uint4*)pV, rV1 = *(const uint4*)(pV + 8);

    // ldmatrix.x4.trans base addresses (A: m=c contiguous; B: n=d contiguous)
    uint32_t aBase = (uint32_t)__cvta_generic_to_shared(
        &sY[(lane & 7) + ((lane & 16) >> 1)][wm * 32 + ((lane & 8) ? 8 : 0)]);
    uint32_t bBase = (uint32_t)__cvta_generic_to_shared(
        &sV[(lane & 15)][wn * 64 + ((lane & 16) ? 8 : 0)]);

    float d[2][8][4];
    #pragma unroll
    for (int i = 0; i < 2; i++)
        #pragma unroll
        for (int j = 0; j < 8; j++)
            #pragma unroll
            for (int q = 0; q < 4; q++) d[i][j][q] = 0.f;

    const int NIT = KCHUNK / BK;  // 64
    for (int it = 0; it < NIT; it++) {
        __syncthreads();
        *(uint4*)&sY[lr][lc]     = rY0;
        *(uint4*)&sY[lr][lc + 8] = rY1;
        *(uint4*)&sV[lr][lc]     = rV0;
        *(uint4*)&sV[lr][lc + 8] = rV1;
        __syncthreads();
        if (it + 1 < NIT) {
            pY += (size_t)BK * CP; pV += (size_t)BK * CP;
            rY0 = *(const uint4*)pY; rY1 = *(const uint4*)(pY + 8);
            rV0 = *(const uint4*)pV; rV1 = *(const uint4*)(pV + 8);
        }
        #pragma unroll
        for (int kk = 0; kk < 2; kk++) {
            uint32_t a[2][4];
            ldm4t(a[0], aBase + (uint32_t)(kk * 16 * SROW) * 2u);
            ldm4t(a[1], aBase + (uint32_t)(kk * 16 * SROW + 16) * 2u);
            uint32_t bb[4][4];
            #pragma unroll
            for (int nt = 0; nt < 4; nt++)
                ldm4t(bb[nt], bBase + (uint32_t)(kk * 16 * SROW + nt * 16) * 2u);
            #pragma unroll
            for (int mt = 0; mt < 2; mt++)
                #pragma unroll
                for (int n = 0; n < 8; n++)
                    mma16816(d[mt][n], a[mt], &bb[n >> 1][(n & 1) * 2]);
        }
    }

    // epilogue: write per-split partial (no atomics -> deterministic)
    float* Gp = g_Gpart[blockIdx.z];
    int g = lane >> 2, tg = lane & 3;
    #pragma unroll
    for (int mt = 0; mt < 2; mt++) {
        #pragma unroll
        for (int n = 0; n < 8; n++) {
            int row = cm + wm * 32 + mt * 16 + g;
            int col = n0 + wn * 64 + n * 8 + tg * 2;
            *(float2*)&Gp[(size_t)row * CP + col]       = make_float2(d[mt][n][0], d[mt][n][1]);
            *(float2*)&Gp[(size_t)(row + 8) * CP + col] = make_float2(d[mt][n][2], d[mt][n][3]);
        }
    }
}

// ---------------- K4: correction = sum co[c,d]*rcp[d]*G[c,d] ----------------
__global__ void k_dot(const float* __restrict__ co) {
    __shared__ float red[8];
    float acc = 0.f;
    for (int idx = blockIdx.x * 256 + threadIdx.x; idx < CDIM * CDIM;
         idx += CORR_BLOCKS * 256) {
        int c  = idx / CDIM;
        int dd = idx - c * CDIM;
        float gs = 0.f;
        #pragma unroll
        for (int s = 0; s < SPLITK; s++) gs += g_Gpart[s][(size_t)c * CP + dd];
        acc += co[idx] * g_rcp[dd] * gs;
    }
    acc = warpRed(acc);
    int warp = threadIdx.x >> 5, lane = threadIdx.x & 31;
    if (lane == 0) red[warp] = acc;
    __syncthreads();
    if (threadIdx.x == 0) {
        float s = 0.f;
        #pragma unroll
        for (int i = 0; i < 8; i++) s += red[i];
        g_corrPart[blockIdx.x] = s;
    }
}

// ---------------- K5: final deterministic reduce ----------------
__global__ void k_final(float* __restrict__ out) {
    __shared__ float red[8];
    float s = 0.f;
    for (int i = threadIdx.x; i < MAIN_BLOCKS; i += 256) s += g_basePart[i];
    for (int i = threadIdx.x; i < CORR_BLOCKS; i += 256) s += g_corrPart[i];
    s = warpRed(s);
    int warp = threadIdx.x >> 5, lane = threadIdx.x & 31;
    if (lane == 0) red[warp] = s;
    __syncthreads();
    if (threadIdx.x == 0) {
        float t = 0.f;
        #pragma unroll
        for (int i = 0; i < 8; i++) t += red[i];
        out[0] = -t;
    }
}

// ---------------- launch ----------------
extern "C" void kernel_launch(void* const* d_in, const int* in_sizes, int n_in,
                              void* d_out, int out_size) {
    const float* x  = (const float*)d_in[0];
    const float* y  = (const float*)d_in[1];
    const float* co = (const float*)d_in[2];
    const float* w  = (const float*)d_in[3];
    float* out = (float*)d_out;

    k_colsum_part<<<dim3(4, 8), 256>>>(co);
    k_finalize_colsum<<<1, 1024>>>();
    k_rowsumM<<<CDIM, 128>>>(co);
    k_main<<<MAIN_BLOCKS, 256>>>(x, y, w);
    k_gemm<<<dim3(8, 8, SPLITK), 256>>>();
    k_dot<<<CORR_BLOCKS, 256>>>(co);
    k_final<<<1, 256>>>(out);
}

// round 3
// speedup vs baseline: 1.4332x; 1.4332x over previous
#include <cuda_runtime.h>
#include <cuda_bf16.h>
#include <cstdint>

#define BDIM 16384
#define CDIM 1000
#define CP   1024
#define SPLITK 8
#define KCHUNK (BDIM / SPLITK)     // 2048
#define MAIN_BLOCKS (BDIM / 8)     // 2048 blocks, warp-per-row
#define CORR_BLOCKS 512

// ---------------- static scratch (no dynamic allocation allowed) ----------------
__device__ float          g_colsumPart[8 * CP];
__device__ float          g_rcp[CP];                       // 1/colsum[d]
__device__ float          g_rowsumM[CP];                   // sum_d M[c,d]
__device__ __nv_bfloat16  g_Y[(size_t)BDIM * CP];          // y (bf16), zero-padded to 1024 cols
__device__ __nv_bfloat16  g_V[(size_t)BDIM * CP];          // V = y*w*h(sigma)/rs  (bf16)
__device__ float          g_Gpart[SPLITK][(size_t)CP * CP];
__device__ float          g_basePart[MAIN_BLOCKS];
__device__ float          g_corrPart[CORR_BLOCKS];

__device__ __forceinline__ float warpRed(float v) {
    #pragma unroll
    for (int o = 16; o; o >>= 1) v += __shfl_xor_sync(0xffffffffu, v, o);
    return v;
}

// ---------------- K1a: partial column sums of co ----------------
__global__ void k_colsum_part(const float* __restrict__ co) {
    int d  = blockIdx.x * 256 + threadIdx.x;   // 0..1023
    int c0 = blockIdx.y * 125;
    float s = 0.f;
    if (d < CDIM) {
        #pragma unroll 5
        for (int c = c0; c < c0 + 125; c++) s += co[(size_t)c * CDIM + d];
    }
    g_colsumPart[blockIdx.y * CP + d] = s;
}

// ---------------- K1b: finalize colsum -> reciprocal ----------------
__global__ void k_finalize_colsum() {
    int d = threadIdx.x;
    float s = 0.f;
    #pragma unroll
    for (int j = 0; j < 8; j++) s += g_colsumPart[j * CP + d];
    g_rcp[d] = (d < CDIM) ? (1.0f / s) : 0.f;
}

// ---------------- K1c: rowsumM[c] = sum_d co[c,d] * rcp[d] ----------------
__global__ void k_rowsumM(const float* __restrict__ co) {
    __shared__ float red[4];
    int c = blockIdx.x;
    float s = 0.f;
    for (int d = threadIdx.x; d < CDIM; d += 128)
        s += co[(size_t)c * CDIM + d] * g_rcp[d];
    s = warpRed(s);
    int warp = threadIdx.x >> 5, lane = threadIdx.x & 31;
    if (lane == 0) red[warp] = s;
    __syncthreads();
    if (threadIdx.x == 0) g_rowsumM[c] = red[0] + red[1] + red[2] + red[3];
}

// ---------------- K2: fused main pass (warp per row) ----------------
// rs_b = y . rowsumM ; base-loss terms ; V = y*w*h(sigma)/rs (bf16) ; Y bf16
__global__ __launch_bounds__(256) void k_main(const float* __restrict__ x,
                                              const float* __restrict__ y,
                                              const float* __restrict__ w) {
    __shared__ float s_rsm[CP];
    __shared__ float s_w[CP];
    __shared__ float s_red[8];
    for (int i = threadIdx.x; i < CP; i += 256) {
        s_rsm[i] = (i < CDIM) ? g_rowsumM[i] : 0.f;
        s_w[i]   = (i < CDIM) ? w[i] : 0.f;
    }
    __syncthreads();

    int warp = threadIdx.x >> 5, lane = threadIdx.x & 31;
    size_t b = (size_t)blockIdx.x * 8 + warp;
    const float* xrow = x + b * CDIM;
    const float* yrow = y + b * CDIM;

    // pass 1: rs = y . rowsumM
    float rs = 0.f;
    #pragma unroll 8
    for (int k = 0; k < 32; k++) {
        int c = k * 32 + lane;
        if (c < CDIM) rs += yrow[c] * s_rsm[c];
    }
    rs = warpRed(rs);
    float rinv = __fdividef(1.0f, rs);

    __nv_bfloat16* Yo = g_Y + b * CP;
    __nv_bfloat16* Vo = g_V + b * CP;

    float base = 0.f;
    #pragma unroll 4
    for (int k = 0; k < 32; k++) {
        int c = k * 32 + lane;                 // c in [0,1024)
        float Vv = 0.f;
        float Yv = 0.f;
        if (c < CDIM) {
            float wv = s_w[c];
            float xv = xrow[c];
            float yc = yrow[c];
            Yv = yc;
            float t   = __expf(-xv);
            float inv = __fdividef(1.f, 1.f + t);   // sigma
            float sig = inv;
            float onems = t * inv;                  // 1 - sigma
            if (yc > 0.5f) {
                float logsig = -__logf(1.f + t);
                base += wv * logsig * onems;
                float h = sig * logsig - onems;     // d(loss)/d(att) factor
                Vv = wv * h * rinv;
            } else {
                float xn  = fminf(onems + 0.05f, 1.f);
                float xn2 = fminf(xn * 1.2f, 1.f);
                float tn  = 1.f - xn2;
                if (tn > 0.f)
                    base += wv * __logf(xn2) * __powf(tn, 3.f + wv);
            }
        }
        Yo[c] = __float2bfloat16(Yv);
        Vo[c] = __float2bfloat16(Vv);
    }
    base = warpRed(base);
    if (lane == 0) s_red[warp] = base;
    __syncthreads();
    if (threadIdx.x == 0) {
        float s = 0.f;
        #pragma unroll
        for (int i = 0; i < 8; i++) s += s_red[i];
        g_basePart[blockIdx.x] = s;
    }
}

// ---------------- K3: G = Y^T V  (bf16 mma.sync, split-K) ----------------
#define BK 32
#define SROW (128 + 8)

__device__ __forceinline__ void ldm4t(uint32_t* r, uint32_t addr) {
    asm volatile("ldmatrix.sync.aligned.m8n8.x4.trans.shared.b16 {%0,%1,%2,%3}, [%4];"
                 : "=r"(r[0]), "=r"(r[1]), "=r"(r[2]), "=r"(r[3]) : "r"(addr));
}
__device__ __forceinline__ void mma16816(float* d, const uint32_t* a, const uint32_t* b) {
    asm volatile("mma.sync.aligned.m16n8k16.row.col.f32.bf16.bf16.f32 "
                 "{%0,%1,%2,%3}, {%4,%5,%6,%7}, {%8,%9}, {%0,%1,%2,%3};"
                 : "+f"(d[0]), "+f"(d[1]), "+f"(d[2]), "+f"(d[3])
                 : "r"(a[0]), "r"(a[1]), "r"(a[2]), "r"(a[3]), "r"(b[0]), "r"(b[1]));
}

__global__ __launch_bounds__(256, 2) void k_gemm() {
    __shared__ __align__(16) __nv_bfloat16 sY[BK][SROW];
    __shared__ __align__(16) __nv_bfloat16 sV[BK][SROW];

    int tid  = threadIdx.x;
    int lane = tid & 31, warp = tid >> 5;
    int wm = warp & 3;            // 4 warps along M (32 rows each)
    int wn = warp >> 2;           // 2 warps along N (64 cols each)
    int cm = blockIdx.y * 128;    // M tile (c)
    int n0 = blockIdx.x * 128;    // N tile (d)
    size_t k0 = (size_t)blockIdx.z * KCHUNK;

    int lr = tid >> 3;            // smem row 0..31
    int lc = (tid & 7) * 16;      // smem col (bf16 units): 16 per thread

    const __nv_bfloat16* pY = g_Y + (k0 + lr) * CP + cm + lc;
    const __nv_bfloat16* pV = g_V + (k0 + lr) * CP + n0 + lc;

    uint4 rY0 = *(const uint4*)pY, rY1 = *(const uint4*)(pY + 8);
    uint4 rV0 = *(const uint4*)pV, rV1 = *(const uint4*)(pV + 8);

    // ldmatrix.x4.trans base addresses (A: m=c contiguous; B: n=d contiguous)
    uint32_t aBase = (uint32_t)__cvta_generic_to_shared(
        &sY[(lane & 7) + ((lane & 16) >> 1)][wm * 32 + ((lane & 8) ? 8 : 0)]);
    uint32_t bBase = (uint32_t)__cvta_generic_to_shared(
        &sV[(lane & 15)][wn * 64 + ((lane & 16) ? 8 : 0)]);

    float d[2][8][4];
    #pragma unroll
    for (int i = 0; i < 2; i++)
        #pragma unroll
        for (int j = 0; j < 8; j++)
            #pragma unroll
            for (int q = 0; q < 4; q++) d[i][j][q] = 0.f;

    const int NIT = KCHUNK / BK;  // 64
    for (int it = 0; it < NIT; it++) {
        __syncthreads();
        *(uint4*)&sY[lr][lc]     = rY0;
        *(uint4*)&sY[lr][lc + 8] = rY1;
        *(uint4*)&sV[lr][lc]     = rV0;
        *(uint4*)&sV[lr][lc + 8] = rV1;
        __syncthreads();
        if (it + 1 < NIT) {
            pY += (size_t)BK * CP; pV += (size_t)BK * CP;
            rY0 = *(const uint4*)pY; rY1 = *(const uint4*)(pY + 8);
            rV0 = *(const uint4*)pV; rV1 = *(const uint4*)(pV + 8);
        }
        #pragma unroll
        for (int kk = 0; kk < 2; kk++) {
            uint32_t a[2][4];
            ldm4t(a[0], aBase + (uint32_t)(kk * 16 * SROW) * 2u);
            ldm4t(a[1], aBase + (uint32_t)(kk * 16 * SROW + 16) * 2u);
            uint32_t bb[4][4];
            #pragma unroll
            for (int nt = 0; nt < 4; nt++)
                ldm4t(bb[nt], bBase + (uint32_t)(kk * 16 * SROW + nt * 16) * 2u);
            #pragma unroll
            for (int mt = 0; mt < 2; mt++)
                #pragma unroll
                for (int n = 0; n < 8; n++)
                    mma16816(d[mt][n], a[mt], &bb[n >> 1][(n & 1) * 2]);
        }
    }

    // epilogue: write per-split partial (no atomics -> deterministic)
    float* Gp = g_Gpart[blockIdx.z];
    int g = lane >> 2, tg = lane & 3;
    #pragma unroll
    for (int mt = 0; mt < 2; mt++) {
        #pragma unroll
        for (int n = 0; n < 8; n++) {
            int row = cm + wm * 32 + mt * 16 + g;
            int col = n0 + wn * 64 + n * 8 + tg * 2;
            *(float2*)&Gp[(size_t)row * CP + col]       = make_float2(d[mt][n][0], d[mt][n][1]);
            *(float2*)&Gp[(size_t)(row + 8) * CP + col] = make_float2(d[mt][n][2], d[mt][n][3]);
        }
    }
}

// ---------------- K4: correction = sum co[c,d]*rcp[d]*G[c,d] ----------------
__global__ void k_dot(const float* __restrict__ co) {
    __shared__ float red[8];
    float acc = 0.f;
    for (int idx = blockIdx.x * 256 + threadIdx.x; idx < CDIM * CDIM;
         idx += CORR_BLOCKS * 256) {
        int c  = idx / CDIM;
        int dd = idx - c * CDIM;
        float gs = 0.f;
        #pragma unroll
        for (int s = 0; s < SPLITK; s++) gs += g_Gpart[s][(size_t)c * CP + dd];
        acc += co[idx] * g_rcp[dd] * gs;
    }
    acc = warpRed(acc);
    int warp = threadIdx.x >> 5, lane = threadIdx.x & 31;
    if (lane == 0) red[warp] = acc;
    __syncthreads();
    if (threadIdx.x == 0) {
        float s = 0.f;
        #pragma unroll
        for (int i = 0; i < 8; i++) s += red[i];
        g_corrPart[blockIdx.x] = s;
    }
}

// ---------------- K5: final deterministic reduce ----------------
__global__ void k_final(float* __restrict__ out) {
    __shared__ float red[8];
    float s = 0.f;
    for (int i = threadIdx.x; i < MAIN_BLOCKS; i += 256) s += g_basePart[i];
    for (int i = threadIdx.x; i < CORR_BLOCKS; i += 256) s += g_corrPart[i];
    s = warpRed(s);
    int warp = threadIdx.x >> 5, lane = threadIdx.x & 31;
    if (lane == 0) red[warp] = s;
    __syncthreads();
    if (threadIdx.x == 0) {
        float t = 0.f;
        #pragma unroll
        for (int i = 0; i < 8; i++) t += red[i];
        out[0] = -t;
    }
}

// ---------------- launch ----------------
extern "C" void kernel_launch(void* const* d_in, const int* in_sizes, int n_in,
                              void* d_out, int out_size) {
    const float* x  = (const float*)d_in[0];
    const float* y  = (const float*)d_in[1];
    const float* co = (const float*)d_in[2];
    const float* w  = (const float*)d_in[3];
    float* out = (float*)d_out;

    k_colsum_part<<<dim3(4, 8), 256>>>(co);
    k_finalize_colsum<<<1, 1024>>>();
    k_rowsumM<<<CDIM, 128>>>(co);
    k_main<<<MAIN_BLOCKS, 256>>>(x, y, w);
    k_gemm<<<dim3(8, 8, SPLITK), 256>>>();
    k_dot<<<CORR_BLOCKS, 256>>>(co);
    k_final<<<1, 256>>>(out);
}

// round 4
// speedup vs baseline: 1.6534x; 1.1537x over previous
#include <cuda_runtime.h>
#include <cuda_bf16.h>
#include <cstdint>

#define BDIM 16384
#define CDIM 1000
#define CP   1024
#define SPLITK 4
#define KCHUNK (BDIM / SPLITK)     // 4096
#define MAIN_BLOCKS (BDIM / 8)     // 2048 blocks, warp-per-row
#define CORR_BLOCKS 512

// ---------------- static scratch (no dynamic allocation allowed) ----------------
__device__ float          g_colsumPart[8 * CP];
__device__ float          g_rcp[CP];                       // 1/colsum[d]
__device__ __align__(16) float g_rowsumM[CP];              // sum_d M[c,d] (pad zeros)
__device__ __align__(128) __nv_bfloat16 g_Y[(size_t)BDIM * CP];
__device__ __align__(128) __nv_bfloat16 g_V[(size_t)BDIM * CP];
__device__ float          g_Gpart[SPLITK][(size_t)CP * CP];
__device__ float          g_basePart[MAIN_BLOCKS];
__device__ float          g_corrPart[CORR_BLOCKS];

__device__ __forceinline__ float warpRed(float v) {
    #pragma unroll
    for (int o = 16; o; o >>= 1) v += __shfl_xor_sync(0xffffffffu, v, o);
    return v;
}

// ---------------- K1a: partial column sums of co ----------------
__global__ void k_colsum_part(const float* __restrict__ co) {
    int d  = blockIdx.x * 256 + threadIdx.x;   // 0..1023
    int c0 = blockIdx.y * 125;
    float s = 0.f;
    if (d < CDIM) {
        #pragma unroll 5
        for (int c = c0; c < c0 + 125; c++) s += co[(size_t)c * CDIM + d];
    }
    g_colsumPart[blockIdx.y * CP + d] = s;
}

// ---------------- K1b: finalize colsum -> reciprocal ----------------
__global__ void k_finalize_colsum() {
    int d = threadIdx.x;
    float s = 0.f;
    #pragma unroll
    for (int j = 0; j < 8; j++) s += g_colsumPart[j * CP + d];
    g_rcp[d] = (d < CDIM) ? (1.0f / s) : 0.f;
}

// ---------------- K1c: rowsumM[c] = sum_d co[c,d] * rcp[d] ----------------
__global__ void k_rowsumM(const float* __restrict__ co) {
    __shared__ float red[4];
    int c = blockIdx.x;
    float s = 0.f;
    for (int d = threadIdx.x; d < CDIM; d += 128)
        s += co[(size_t)c * CDIM + d] * g_rcp[d];
    s = warpRed(s);
    int warp = threadIdx.x >> 5, lane = threadIdx.x & 31;
    if (lane == 0) red[warp] = s;
    __syncthreads();
    if (threadIdx.x == 0) g_rowsumM[c] = red[0] + red[1] + red[2] + red[3];
}

// ---------------- K2: fused main pass (warp per row, float4 path) ----------------
__global__ __launch_bounds__(256) void k_main(const float* __restrict__ x,
                                              const float* __restrict__ y,
                                              const float* __restrict__ w) {
    __shared__ float4 s_rsm4[256];
    __shared__ float4 s_w4[256];
    __shared__ float  s_red[8];
    {
        int t = threadIdx.x;
        if (t < 250) {
            s_rsm4[t] = ((const float4*)g_rowsumM)[t];
            s_w4[t]   = ((const float4*)w)[t];
        } else {
            s_rsm4[t] = make_float4(0.f, 0.f, 0.f, 0.f);
            s_w4[t]   = make_float4(0.f, 0.f, 0.f, 0.f);
        }
    }
    __syncthreads();

    int warp = threadIdx.x >> 5, lane = threadIdx.x & 31;
    size_t b = (size_t)blockIdx.x * 8 + warp;
    const float4* x4 = (const float4*)(x + b * CDIM);  // 4000B row stride, 16B aligned
    const float4* y4 = (const float4*)(y + b * CDIM);

    // pass 1: load y into regs, rs = y . rowsumM
    float4 yreg[8];
    float rs = 0.f;
    #pragma unroll
    for (int k = 0; k < 8; k++) {
        int idx = k * 32 + lane;
        if (idx < 250) {
            float4 yv = y4[idx];
            yreg[k] = yv;
            float4 rm = s_rsm4[idx];
            rs += yv.x * rm.x + yv.y * rm.y + yv.z * rm.z + yv.w * rm.w;
        } else {
            yreg[k] = make_float4(0.f, 0.f, 0.f, 0.f);
        }
    }
    rs = warpRed(rs);
    float rinv = __fdividef(1.0f, rs);

    __nv_bfloat16* Yo = g_Y + b * CP;
    __nv_bfloat16* Vo = g_V + b * CP;

    float base = 0.f;
    #pragma unroll
    for (int k = 0; k < 8; k++) {
        int idx = k * 32 + lane;
        float4 xv = (idx < 250) ? x4[idx] : make_float4(0.f, 0.f, 0.f, 0.f);
        float4 yv = yreg[k];
        float4 wv = (idx < 250) ? s_w4[idx] : make_float4(0.f, 0.f, 0.f, 0.f);
        float Yv[4], Vv[4];
        const float* xp = &xv.x; const float* yp = &yv.x; const float* wp = &wv.x;
        #pragma unroll
        for (int j = 0; j < 4; j++) {
            float xe = xp[j], ye = yp[j], we = wp[j];
            Yv[j] = ye; Vv[j] = 0.f;
            if (idx < 250) {
                float t     = __expf(-xe);
                float inv   = __fdividef(1.f, 1.f + t);   // sigma
                float onems = t * inv;                    // 1 - sigma
                if (ye > 0.5f) {
                    float logsig = -__logf(1.f + t);
                    base += we * logsig * onems;
                    Vv[j] = we * (inv * logsig - onems) * rinv;
                } else {
                    float xn  = fminf(onems + 0.05f, 1.f);
                    float xn2 = fminf(xn * 1.2f, 1.f);
                    float tn  = 1.f - xn2;
                    if (tn > 0.f)
                        base += we * __logf(xn2) * __powf(tn, 3.f + we);
                }
            } else {
                Yv[j] = 0.f;  // padding cols [1000,1024)
            }
        }
        union { __nv_bfloat16 h[4]; uint2 u; } py, pv;
        #pragma unroll
        for (int j = 0; j < 4; j++) { py.h[j] = __float2bfloat16(Yv[j]); pv.h[j] = __float2bfloat16(Vv[j]); }
        *(uint2*)&Yo[idx * 4] = py.u;
        *(uint2*)&Vo[idx * 4] = pv.u;
    }
    base = warpRed(base);
    if (lane == 0) s_red[warp] = base;
    __syncthreads();
    if (threadIdx.x == 0) {
        float s = 0.f;
        #pragma unroll
        for (int i = 0; i < 8; i++) s += s_red[i];
        g_basePart[blockIdx.x] = s;
    }
}

// ---------------- K3: G = Y^T V  (bf16 mma.sync, cp.async 2-stage, BK=64) ----------------
#define BK 64
#define SROW 136
#define STAGE_ELEMS (2 * BK * SROW)   // 17408 bf16 per stage (Y then V)
#define VOFF (BK * SROW)              // 8704

__device__ __forceinline__ void ldm4t(uint32_t* r, uint32_t addr) {
    asm volatile("ldmatrix.sync.aligned.m8n8.x4.trans.shared.b16 {%0,%1,%2,%3}, [%4];"
                 : "=r"(r[0]), "=r"(r[1]), "=r"(r[2]), "=r"(r[3]) : "r"(addr));
}
__device__ __forceinline__ void mma16816(float* d, const uint32_t* a, const uint32_t* b) {
    asm volatile("mma.sync.aligned.m16n8k16.row.col.f32.bf16.bf16.f32 "
                 "{%0,%1,%2,%3}, {%4,%5,%6,%7}, {%8,%9}, {%0,%1,%2,%3};"
                 : "+f"(d[0]), "+f"(d[1]), "+f"(d[2]), "+f"(d[3])
                 : "r"(a[0]), "r"(a[1]), "r"(a[2]), "r"(a[3]), "r"(b[0]), "r"(b[1]));
}
__device__ __forceinline__ void cpa16(uint32_t dst, const void* src) {
    asm volatile("cp.async.cg.shared.global [%0], [%1], 16;" :: "r"(dst), "l"(src));
}
__device__ __forceinline__ void cpa_commit() { asm volatile("cp.async.commit_group;"); }
__device__ __forceinline__ void cpa_wait1()  { asm volatile("cp.async.wait_group 1;"); }
__device__ __forceinline__ void cpa_wait0()  { asm volatile("cp.async.wait_group 0;"); }

__global__ __launch_bounds__(256) void k_gemm() {
    extern __shared__ __nv_bfloat16 smem[];   // 2 stages x (sY | sV)

    int tid  = threadIdx.x;
    int lane = tid & 31, warp = tid >> 5;
    int wm = warp & 3;            // 4 warps along M (32 rows each)
    int wn = warp >> 2;           // 2 warps along N (64 cols each)
    int cm = blockIdx.y * 128;    // M tile (c)
    int n0 = blockIdx.x * 128;    // N tile (d)
    size_t k0 = (size_t)blockIdx.z * KCHUNK;

    uint32_t sbase = (uint32_t)__cvta_generic_to_shared(smem);

    // cp.async layout: thread -> (row16 = tid>>4 in [0,16), colc = (tid&15)*8)
    int row16 = tid >> 4;
    int colc  = (tid & 15) * 8;

    const __nv_bfloat16* gy = g_Y + (k0 + row16) * CP + cm + colc;
    const __nv_bfloat16* gv = g_V + (k0 + row16) * CP + n0 + colc;

    // ldmatrix base offsets (elements) within a stage, kept identical to R2 layout
    uint32_t aOff = (uint32_t)(((lane & 7) + ((lane & 16) >> 1)) * SROW + wm * 32 + ((lane & 8) ? 8 : 0));
    uint32_t bOff = (uint32_t)((lane & 15) * SROW + wn * 64 + ((lane & 16) ? 8 : 0));

    float d[2][8][4];
    #pragma unroll
    for (int i = 0; i < 2; i++)
        #pragma unroll
        for (int j = 0; j < 8; j++)
            #pragma unroll
            for (int q = 0; q < 4; q++) d[i][j][q] = 0.f;

    const int NIT = KCHUNK / BK;  // 64

    auto load_stage = [&](int it, int s) {
        uint32_t dY = sbase + 2u * (uint32_t)(s * STAGE_ELEMS + row16 * SROW + colc);
        uint32_t dV = dY + 2u * VOFF;
        const __nv_bfloat16* pY = gy + (size_t)it * BK * CP;
        const __nv_bfloat16* pV = gv + (size_t)it * BK * CP;
        #pragma unroll
        for (int r = 0; r < 4; r++) {
            cpa16(dY + 2u * (uint32_t)(r * 16 * SROW), pY + (size_t)r * 16 * CP);
            cpa16(dV + 2u * (uint32_t)(r * 16 * SROW), pV + (size_t)r * 16 * CP);
        }
        cpa_commit();
    };

    load_stage(0, 0);

    for (int it = 0; it < NIT; it++) {
        int s = it & 1;
        bool more = (it + 1 < NIT);
        if (more) load_stage(it + 1, s ^ 1);
        if (more) cpa_wait1(); else cpa_wait0();
        __syncthreads();

        uint32_t stageB = sbase + 2u * (uint32_t)(s * STAGE_ELEMS);
        #pragma unroll
        for (int kk = 0; kk < 4; kk++) {
            uint32_t kbB = stageB + 2u * (uint32_t)(kk * 16 * SROW);
            uint32_t a[2][4];
            ldm4t(a[0], kbB + 2u * aOff);
            ldm4t(a[1], kbB + 2u * (aOff + 16));
            uint32_t bb[4][4];
            #pragma unroll
            for (int nt = 0; nt < 4; nt++)
                ldm4t(bb[nt], kbB + 2u * (VOFF + bOff + nt * 16));
            #pragma unroll
            for (int mt = 0; mt < 2; mt++)
                #pragma unroll
                for (int n = 0; n < 8; n++)
                    mma16816(d[mt][n], a[mt], &bb[n >> 1][(n & 1) * 2]);
        }
        __syncthreads();
    }

    // epilogue: per-split partials (no atomics -> deterministic)
    float* Gp = g_Gpart[blockIdx.z];
    int g = lane >> 2, tg = lane & 3;
    #pragma unroll
    for (int mt = 0; mt < 2; mt++) {
        #pragma unroll
        for (int n = 0; n < 8; n++) {
            int row = cm + wm * 32 + mt * 16 + g;
            int col = n0 + wn * 64 + n * 8 + tg * 2;
            *(float2*)&Gp[(size_t)row * CP + col]       = make_float2(d[mt][n][0], d[mt][n][1]);
            *(float2*)&Gp[(size_t)(row + 8) * CP + col] = make_float2(d[mt][n][2], d[mt][n][3]);
        }
    }
}

// ---------------- K4: correction = sum co[c,d]*rcp[d]*G[c,d] ----------------
__global__ void k_dot(const float* __restrict__ co) {
    __shared__ float red[8];
    float acc = 0.f;
    for (int idx = blockIdx.x * 256 + threadIdx.x; idx < CDIM * CDIM;
         idx += CORR_BLOCKS * 256) {
        int c  = idx / CDIM;
        int dd = idx - c * CDIM;
        float gs = 0.f;
        #pragma unroll
        for (int s = 0; s < SPLITK; s++) gs += g_Gpart[s][(size_t)c * CP + dd];
        acc += co[idx] * g_rcp[dd] * gs;
    }
    acc = warpRed(acc);
    int warp = threadIdx.x >> 5, lane = threadIdx.x & 31;
    if (lane == 0) red[warp] = acc;
    __syncthreads();
    if (threadIdx.x == 0) {
        float s = 0.f;
        #pragma unroll
        for (int i = 0; i < 8; i++) s += red[i];
        g_corrPart[blockIdx.x] = s;
    }
}

// ---------------- K5: final deterministic reduce ----------------
__global__ void k_final(float* __restrict__ out) {
    __shared__ float red[8];
    float s = 0.f;
    for (int i = threadIdx.x; i < MAIN_BLOCKS; i += 256) s += g_basePart[i];
    for (int i = threadIdx.x; i < CORR_BLOCKS; i += 256) s += g_corrPart[i];
    s = warpRed(s);
    int warp = threadIdx.x >> 5, lane = threadIdx.x & 31;
    if (lane == 0) red[warp] = s;
    __syncthreads();
    if (threadIdx.x == 0) {
        float t = 0.f;
        #pragma unroll
        for (int i = 0; i < 8; i++) t += red[i];
        out[0] = -t;
    }
}

// ---------------- launch ----------------
extern "C" void kernel_launch(void* const* d_in, const int* in_sizes, int n_in,
                              void* d_out, int out_size) {
    const float* x  = (const float*)d_in[0];
    const float* y  = (const float*)d_in[1];
    const float* co = (const float*)d_in[2];
    const float* w  = (const float*)d_in[3];
    float* out = (float*)d_out;

    const int gemm_smem = 2 * STAGE_ELEMS * (int)sizeof(__nv_bfloat16);  // 69632
    cudaFuncSetAttribute(k_gemm, cudaFuncAttributeMaxDynamicSharedMemorySize, gemm_smem);

    k_colsum_part<<<dim3(4, 8), 256>>>(co);
    k_finalize_colsum<<<1, 1024>>>();
    k_rowsumM<<<CDIM, 128>>>(co);
    k_main<<<MAIN_BLOCKS, 256>>>(x, y, w);
    k_gemm<<<dim3(8, 8, SPLITK), 256, gemm_smem>>>();
    k_dot<<<CORR_BLOCKS, 256>>>(co);
    k_final<<<1, 256>>>(out);
}

// round 5
// speedup vs baseline: 1.6684x; 1.0091x over previous
#include <cuda_runtime.h>
#include <cuda_bf16.h>
#include <cstdint>

#define BDIM 16384
#define CDIM 1000
#define CP   1024
#define SPLITK 4
#define KCHUNK (BDIM / SPLITK)     // 4096
#define MAIN_BLOCKS (BDIM / 8)     // 2048 blocks, warp-per-row
#define CORR_BLOCKS 512

// ---------------- static scratch (no dynamic allocation allowed) ----------------
__device__ float          g_colsumPart[8 * CP];
__device__ float          g_rcp[CP];                       // 1/colsum[d]
__device__ __align__(16) float g_rowsumM[CP];              // sum_d M[c,d] (pad zeros)
__device__ __align__(128) __nv_bfloat16 g_Y[(size_t)BDIM * CP];
__device__ __align__(128) __nv_bfloat16 g_V[(size_t)BDIM * CP];
__device__ float          g_Gpart[SPLITK][(size_t)CP * CP];
__device__ float          g_basePart[MAIN_BLOCKS];
__device__ float          g_corrPart[CORR_BLOCKS];

__device__ __forceinline__ float warpRed(float v) {
    #pragma unroll
    for (int o = 16; o; o >>= 1) v += __shfl_xor_sync(0xffffffffu, v, o);
    return v;
}

// ---------------- K1a: partial column sums of co ----------------
__global__ void k_colsum_part(const float* __restrict__ co) {
    int d  = blockIdx.x * 256 + threadIdx.x;   // 0..1023
    int c0 = blockIdx.y * 125;
    float s = 0.f;
    if (d < CDIM) {
        #pragma unroll 5
        for (int c = c0; c < c0 + 125; c++) s += co[(size_t)c * CDIM + d];
    }
    g_colsumPart[blockIdx.y * CP + d] = s;
}

// ---------------- K1b: finalize colsum -> reciprocal ----------------
__global__ void k_finalize_colsum() {
    int d = threadIdx.x;
    float s = 0.f;
    #pragma unroll
    for (int j = 0; j < 8; j++) s += g_colsumPart[j * CP + d];
    g_rcp[d] = (d < CDIM) ? (1.0f / s) : 0.f;
}

// ---------------- K1c: rowsumM[c] = sum_d co[c,d] * rcp[d] ----------------
__global__ void k_rowsumM(const float* __restrict__ co) {
    __shared__ float red[4];
    int c = blockIdx.x;
    float s = 0.f;
    for (int d = threadIdx.x; d < CDIM; d += 128)
        s += co[(size_t)c * CDIM + d] * g_rcp[d];
    s = warpRed(s);
    int warp = threadIdx.x >> 5, lane = threadIdx.x & 31;
    if (lane == 0) red[warp] = s;
    __syncthreads();
    if (threadIdx.x == 0) g_rowsumM[c] = red[0] + red[1] + red[2] + red[3];
}

// ---------------- K2: fused main pass (warp per row, float4 path) ----------------
__global__ __launch_bounds__(256) void k_main(const float* __restrict__ x,
                                              const float* __restrict__ y,
                                              const float* __restrict__ w) {
    __shared__ float4 s_rsm4[256];
    __shared__ float4 s_w4[256];
    __shared__ float  s_red[8];
    {
        int t = threadIdx.x;
        if (t < 250) {
            s_rsm4[t] = ((const float4*)g_rowsumM)[t];
            s_w4[t]   = ((const float4*)w)[t];
        } else {
            s_rsm4[t] = make_float4(0.f, 0.f, 0.f, 0.f);
            s_w4[t]   = make_float4(0.f, 0.f, 0.f, 0.f);
        }
    }
    __syncthreads();

    int warp = threadIdx.x >> 5, lane = threadIdx.x & 31;
    size_t b = (size_t)blockIdx.x * 8 + warp;
    const float4* x4 = (const float4*)(x + b * CDIM);  // 4000B row stride, 16B aligned
    const float4* y4 = (const float4*)(y + b * CDIM);

    // pass 1: load y into regs, rs = y . rowsumM
    float4 yreg[8];
    float rs = 0.f;
    #pragma unroll
    for (int k = 0; k < 8; k++) {
        int idx = k * 32 + lane;
        if (idx < 250) {
            float4 yv = y4[idx];
            yreg[k] = yv;
            float4 rm = s_rsm4[idx];
            rs += yv.x * rm.x + yv.y * rm.y + yv.z * rm.z + yv.w * rm.w;
        } else {
            yreg[k] = make_float4(0.f, 0.f, 0.f, 0.f);
        }
    }
    rs = warpRed(rs);
    float rinv = __fdividef(1.0f, rs);

    __nv_bfloat16* Yo = g_Y + b * CP;
    __nv_bfloat16* Vo = g_V + b * CP;

    float base = 0.f;
    #pragma unroll
    for (int k = 0; k < 8; k++) {
        int idx = k * 32 + lane;
        float4 xv = (idx < 250) ? x4[idx] : make_float4(0.f, 0.f, 0.f, 0.f);
        float4 yv = yreg[k];
        float4 wv = (idx < 250) ? s_w4[idx] : make_float4(0.f, 0.f, 0.f, 0.f);
        float Yv[4], Vv[4];
        const float* xp = &xv.x; const float* yp = &yv.x; const float* wp = &wv.x;
        #pragma unroll
        for (int j = 0; j < 4; j++) {
            float xe = xp[j], ye = yp[j], we = wp[j];
            Yv[j] = ye; Vv[j] = 0.f;
            if (idx < 250) {
                float t     = __expf(-xe);
                float inv   = __fdividef(1.f, 1.f + t);   // sigma
                float onems = t * inv;                    // 1 - sigma
                if (ye > 0.5f) {
                    float logsig = -__logf(1.f + t);
                    base += we * logsig * onems;
                    Vv[j] = we * (inv * logsig - onems) * rinv;
                } else {
                    float xn  = fminf(onems + 0.05f, 1.f);
                    float xn2 = fminf(xn * 1.2f, 1.f);
                    float tn  = 1.f - xn2;
                    if (tn > 0.f)
                        base += we * __logf(xn2) * __powf(tn, 3.f + we);
                }
            } else {
                Yv[j] = 0.f;  // padding cols [1000,1024)
            }
        }
        union { __nv_bfloat16 h[4]; uint2 u; } py, pv;
        #pragma unroll
        for (int j = 0; j < 4; j++) { py.h[j] = __float2bfloat16(Yv[j]); pv.h[j] = __float2bfloat16(Vv[j]); }
        *(uint2*)&Yo[idx * 4] = py.u;
        *(uint2*)&Vo[idx * 4] = pv.u;
    }
    base = warpRed(base);
    if (lane == 0) s_red[warp] = base;
    __syncthreads();
    if (threadIdx.x == 0) {
        float s = 0.f;
        #pragma unroll
        for (int i = 0; i < 8; i++) s += s_red[i];
        g_basePart[blockIdx.x] = s;
    }
}

// ---------------- K3: G = Y^T V  (bf16 mma.sync, cp.async 2-stage, BK=64) ----------------
#define BK 64
#define SROW 136
#define STAGE_ELEMS (2 * BK * SROW)   // 17408 bf16 per stage (Y then V)
#define VOFF (BK * SROW)              // 8704

__device__ __forceinline__ void ldm4t(uint32_t* r, uint32_t addr) {
    asm volatile("ldmatrix.sync.aligned.m8n8.x4.trans.shared.b16 {%0,%1,%2,%3}, [%4];"
                 : "=r"(r[0]), "=r"(r[1]), "=r"(r[2]), "=r"(r[3]) : "r"(addr));
}
__device__ __forceinline__ void mma16816(float* d, const uint32_t* a, const uint32_t* b) {
    asm volatile("mma.sync.aligned.m16n8k16.row.col.f32.bf16.bf16.f32 "
                 "{%0,%1,%2,%3}, {%4,%5,%6,%7}, {%8,%9}, {%0,%1,%2,%3};"
                 : "+f"(d[0]), "+f"(d[1]), "+f"(d[2]), "+f"(d[3])
                 : "r"(a[0]), "r"(a[1]), "r"(a[2]), "r"(a[3]), "r"(b[0]), "r"(b[1]));
}
__device__ __forceinline__ void cpa16(uint32_t dst, const void* src) {
    asm volatile("cp.async.cg.shared.global [%0], [%1], 16;" :: "r"(dst), "l"(src));
}
__device__ __forceinline__ void cpa_commit() { asm volatile("cp.async.commit_group;"); }
__device__ __forceinline__ void cpa_wait1()  { asm volatile("cp.async.wait_group 1;"); }
__device__ __forceinline__ void cpa_wait0()  { asm volatile("cp.async.wait_group 0;"); }

__global__ __launch_bounds__(256) void k_gemm() {
    extern __shared__ __nv_bfloat16 smem[];   // 2 stages x (sY | sV)

    int tid  = threadIdx.x;
    int lane = tid & 31, warp = tid >> 5;
    int wm = warp & 3;            // 4 warps along M (32 rows each)
    int wn = warp >> 2;           // 2 warps along N (64 cols each)
    int cm = blockIdx.y * 128;    // M tile (c)
    int n0 = blockIdx.x * 128;    // N tile (d)
    size_t k0 = (size_t)blockIdx.z * KCHUNK;

    uint32_t sbase = (uint32_t)__cvta_generic_to_shared(smem);

    // cp.async layout: thread -> (row16 = tid>>4 in [0,16), colc = (tid&15)*8)
    int row16 = tid >> 4;
    int colc  = (tid & 15) * 8;

    const __nv_bfloat16* gy = g_Y + (k0 + row16) * CP + cm + colc;
    const __nv_bfloat16* gv = g_V + (k0 + row16) * CP + n0 + colc;

    // ldmatrix base offsets (elements) within a stage, kept identical to R2 layout
    uint32_t aOff = (uint32_t)(((lane & 7) + ((lane & 16) >> 1)) * SROW + wm * 32 + ((lane & 8) ? 8 : 0));
    uint32_t bOff = (uint32_t)((lane & 15) * SROW + wn * 64 + ((lane & 16) ? 8 : 0));

    float d[2][8][4];
    #pragma unroll
    for (int i = 0; i < 2; i++)
        #pragma unroll
        for (int j = 0; j < 8; j++)
            #pragma unroll
            for (int q = 0; q < 4; q++) d[i][j][q] = 0.f;

    const int NIT = KCHUNK / BK;  // 64

    auto load_stage = [&](int it, int s) {
        uint32_t dY = sbase + 2u * (uint32_t)(s * STAGE_ELEMS + row16 * SROW + colc);
        uint32_t dV = dY + 2u * VOFF;
        const __nv_bfloat16* pY = gy + (size_t)it * BK * CP;
        const __nv_bfloat16* pV = gv + (size_t)it * BK * CP;
        #pragma unroll
        for (int r = 0; r < 4; r++) {
            cpa16(dY + 2u * (uint32_t)(r * 16 * SROW), pY + (size_t)r * 16 * CP);
            cpa16(dV + 2u * (uint32_t)(r * 16 * SROW), pV + (size_t)r * 16 * CP);
        }
        cpa_commit();
    };

    load_stage(0, 0);

    for (int it = 0; it < NIT; it++) {
        int s = it & 1;
        bool more = (it + 1 < NIT);
        if (more) load_stage(it + 1, s ^ 1);
        if (more) cpa_wait1(); else cpa_wait0();
        __syncthreads();

        uint32_t stageB = sbase + 2u * (uint32_t)(s * STAGE_ELEMS);
        #pragma unroll
        for (int kk = 0; kk < 4; kk++) {
            uint32_t kbB = stageB + 2u * (uint32_t)(kk * 16 * SROW);
            uint32_t a[2][4];
            ldm4t(a[0], kbB + 2u * aOff);
            ldm4t(a[1], kbB + 2u * (aOff + 16));
            uint32_t bb[4][4];
            #pragma unroll
            for (int nt = 0; nt < 4; nt++)
                ldm4t(bb[nt], kbB + 2u * (VOFF + bOff + nt * 16));
            #pragma unroll
            for (int mt = 0; mt < 2; mt++)
                #pragma unroll
                for (int n = 0; n < 8; n++)
                    mma16816(d[mt][n], a[mt], &bb[n >> 1][(n & 1) * 2]);
        }
        __syncthreads();
    }

    // epilogue: per-split partials (no atomics -> deterministic)
    float* Gp = g_Gpart[blockIdx.z];
    int g = lane >> 2, tg = lane & 3;
    #pragma unroll
    for (int mt = 0; mt < 2; mt++) {
        #pragma unroll
        for (int n = 0; n < 8; n++) {
            int row = cm + wm * 32 + mt * 16 + g;
            int col = n0 + wn * 64 + n * 8 + tg * 2;
            *(float2*)&Gp[(size_t)row * CP + col]       = make_float2(d[mt][n][0], d[mt][n][1]);
            *(float2*)&Gp[(size_t)(row + 8) * CP + col] = make_float2(d[mt][n][2], d[mt][n][3]);
        }
    }
}

// ---------------- K4: correction = sum co[c,d]*rcp[d]*G[c,d] ----------------
__global__ void k_dot(const float* __restrict__ co) {
    __shared__ float red[8];
    float acc = 0.f;
    for (int idx = blockIdx.x * 256 + threadIdx.x; idx < CDIM * CDIM;
         idx += CORR_BLOCKS * 256) {
        int c  = idx / CDIM;
        int dd = idx - c * CDIM;
        float gs = 0.f;
        #pragma unroll
        for (int s = 0; s < SPLITK; s++) gs += g_Gpart[s][(size_t)c * CP + dd];
        acc += co[idx] * g_rcp[dd] * gs;
    }
    acc = warpRed(acc);
    int warp = threadIdx.x >> 5, lane = threadIdx.x & 31;
    if (lane == 0) red[warp] = acc;
    __syncthreads();
    if (threadIdx.x == 0) {
        float s = 0.f;
        #pragma unroll
        for (int i = 0; i < 8; i++) s += red[i];
        g_corrPart[blockIdx.x] = s;
    }
}

// ---------------- K5: final deterministic reduce ----------------
__global__ void k_final(float* __restrict__ out) {
    __shared__ float red[8];
    float s = 0.f;
    for (int i = threadIdx.x; i < MAIN_BLOCKS; i += 256) s += g_basePart[i];
    for (int i = threadIdx.x; i < CORR_BLOCKS; i += 256) s += g_corrPart[i];
    s = warpRed(s);
    int warp = threadIdx.x >> 5, lane = threadIdx.x & 31;
    if (lane == 0) red[warp] = s;
    __syncthreads();
    if (threadIdx.x == 0) {
        float t = 0.f;
        #pragma unroll
        for (int i = 0; i < 8; i++) t += red[i];
        out[0] = -t;
    }
}

// ---------------- launch ----------------
extern "C" void kernel_launch(void* const* d_in, const int* in_sizes, int n_in,
                              void* d_out, int out_size) {
    const float* x  = (const float*)d_in[0];
    const float* y  = (const float*)d_in[1];
    const float* co = (const float*)d_in[2];
    const float* w  = (const float*)d_in[3];
    float* out = (float*)d_out;

    const int gemm_smem = 2 * STAGE_ELEMS * (int)sizeof(__nv_bfloat16);  // 69632
    cudaFuncSetAttribute(k_gemm, cudaFuncAttributeMaxDynamicSharedMemorySize, gemm_smem);

    k_colsum_part<<<dim3(4, 8), 256>>>(co);
    k_finalize_colsum<<<1, 1024>>>();
    k_rowsumM<<<CDIM, 128>>>(co);
    k_main<<<MAIN_BLOCKS, 256>>>(x, y, w);
    k_gemm<<<dim3(8, 8, SPLITK), 256, gemm_smem>>>();
    k_dot<<<CORR_BLOCKS, 256>>>(co);
    k_final<<<1, 256>>>(out);
}